// round 16
// baseline (speedup 1.0000x reference)
#include <cuda_runtime.h>
#include <cuda_fp16.h>
#include <cstdint>

#define GNB 64
#define NTHR 256
typedef unsigned u32;
typedef unsigned long long u64;

// -------- device scratch --------
__device__ float d_XP[(size_t)64 * 512 * 3072];            // x-projections (+bias)
__device__ float d_hF0[1024 * 64];                         // final h [col][b] for head
__device__ __align__(16) unsigned short d_h16[64 * 1024];  // h fp16 [b][k]
__device__ __align__(16) unsigned short d_rh16[64 * 1024]; // r*h fp16 [b][k]
__device__ unsigned d_count;                               // monotone barrier counter

// smem byte offsets (gru kernel)
#define WA_OFF 0          // [32 rows][1024 k] fp16 swizzled (rows 0-15 Whz cols, 16-31 Whr cols)
#define WB_OFF 65536      // [16 rows][1024 k] fp16 swizzled (Whh cols)
#define RED_OFF 98304     // [4][32][68] fp32 reduction
#define ZL_OFF 133120     // zloc [16][64] fp32
#define HL_OFF 137216     // hloc [16][64] fp32
#define SMEM_BYTES 141312

// -------- helpers --------
__device__ __forceinline__ u64 dup2(float x){u64 r;asm("mov.b64 %0,{%1,%1};":"=l"(r):"f"(x));return r;}
__device__ __forceinline__ void fma2(u64&a,u64 x,u64 y){asm("fma.rn.f32x2 %0,%1,%2,%0;":"+l"(a):"l"(x),"l"(y));}
__device__ __forceinline__ float2 unp2(u64 v){float2 f;asm("mov.b64 {%0,%1},%2;":"=f"(f.x),"=f"(f.y):"l"(v));return f;}
__device__ __forceinline__ void lds128(u64&a,u64&b,unsigned ad){asm volatile("ld.shared.v2.u64 {%0,%1},[%2];":"=l"(a),"=l"(b):"r"(ad));}
__device__ __forceinline__ float sigmoidf(float x){return 1.f/(1.f+__expf(-x));}

__device__ __forceinline__ void mma_f16(float* c,const u32* a,const u32* b){
    asm volatile("mma.sync.aligned.m16n8k16.row.col.f32.f16.f16.f32 "
        "{%0,%1,%2,%3},{%4,%5,%6,%7},{%8,%9},{%0,%1,%2,%3};"
        : "+f"(c[0]),"+f"(c[1]),"+f"(c[2]),"+f"(c[3])
        : "r"(a[0]),"r"(a[1]),"r"(a[2]),"r"(a[3]),"r"(b[0]),"r"(b[1]));
}
__device__ __forceinline__ unsigned short h16(float x){
    return __half_as_ushort(__float2half_rn(x));
}
__device__ __forceinline__ u32 packu(unsigned short a,unsigned short b){
    return (u32)a|((u32)b<<16);
}
__device__ __forceinline__ int swz(int row,int w){return w^((row&7)<<2);}
__device__ __forceinline__ u32 ldcg32(const unsigned short* p){
    u32 v;asm volatile("ld.global.cg.b32 %0,[%1];":"=r"(v):"l"(p));return v;
}

// single-counter monotone grid barrier (release/acquire), 64 arrivals
__device__ __forceinline__ void gridbar(){
    __syncthreads();
    if(threadIdx.x==0){
        unsigned a;
        asm volatile("atom.add.release.gpu.u32 %0,[%1],%2;"
                     :"=r"(a):"l"(&d_count),"r"(1u):"memory");
        unsigned tg=a-(a&(GNB-1))+GNB,cur;
        do{asm volatile("ld.acquire.gpu.u32 %0,[%1];":"=r"(cur):"l"(&d_count));}while((int)(cur-tg)<0);
    }
    __syncthreads();
}

// -------- xproj (fp32, proven) --------
__global__ void __launch_bounds__(256) xproj_kernel(
    const float* __restrict__ x,
    const float* __restrict__ Wxz,const float* __restrict__ Wxr,const float* __restrict__ Wxh,
    const float* __restrict__ bz,const float* __restrict__ br,const float* __restrict__ bh){
    __shared__ float As[64*68],Bs[64*68];
    const int tid=threadIdx.x,ct=blockIdx.x,rt=blockIdx.y,wsel=ct>>4;
    const float* W=(wsel==0)?Wxz:((wsel==1)?Wxr:Wxh);
    const float* bias=(wsel==0)?bz:((wsel==1)?br:bh);
    const int colbase=(ct&15)*64,row0=rt*64,r4=(tid>>4)*4,c4=(tid&15)*4;
    u64 acc[4][2]={};
    for(int k0=0;k0<256;k0+=64){
        __syncthreads();
#pragma unroll
        for(int i=0;i<4;i++){int q=tid+i*256,rr=q>>4,kq=q&15;
            *(float4*)&As[rr*68+kq*4]=*(const float4*)&x[(size_t)(row0+rr)*256+k0+kq*4];}
#pragma unroll
        for(int i=0;i<4;i++){int q=tid+i*256,kk=q>>4,cq=q&15;
            *(float4*)&Bs[kk*68+cq*4]=*(const float4*)&W[(size_t)(k0+kk)*1024+colbase+cq*4];}
        __syncthreads();
        unsigned bs=(unsigned)__cvta_generic_to_shared(&Bs[c4]);
#pragma unroll 8
        for(int kk=0;kk<64;kk++){
            u64 bL,bH;lds128(bL,bH,bs+kk*68*4);
#pragma unroll
            for(int i=0;i<4;i++){u64 ad=dup2(As[(r4+i)*68+kk]);fma2(acc[i][0],ad,bL);fma2(acc[i][1],ad,bH);}
        }
    }
    float4 bb=*(const float4*)&bias[colbase+c4];
#pragma unroll
    for(int i=0;i<4;i++){
        float2 lo=unp2(acc[i][0]),hi=unp2(acc[i][1]);
        *(float4*)&d_XP[(size_t)(row0+r4+i)*3072+ct*64+c4]=make_float4(lo.x+bb.x,lo.y+bb.y,hi.x+bb.z,hi.y+bb.w);
    }
}

// -------- persistent GRU: 64 blocks, gate-colocated cols, 2 exchange legs/step --------
__global__ void __launch_bounds__(NTHR,1) gru_kernel(
    const float* __restrict__ Whz,const float* __restrict__ Whr,const float* __restrict__ Whh){
    extern __shared__ char smc[];
    unsigned short* wa=(unsigned short*)(smc+WA_OFF);
    unsigned short* wb=(unsigned short*)(smc+WB_OFF);
    float* red=(float*)(smc+RED_OFF);      // [kw][32 rows][68]
    float* zl =(float*)(smc+ZL_OFF);       // [16][64]
    float* hl =(float*)(smc+HL_OFF);       // [16][64]
    const int tid=threadIdx.x,bid=blockIdx.x,wid=tid>>5,lane=tid&31;
    const int g=lane>>2,tk=(lane&3)*2;
    const int nw=wid&1,kw=wid>>1;          // 2 n-slices x 4 k-slices

    // ---- weights -> smem fp16 swizzled ----
#pragma unroll 8
    for(int i=0;i<64;i++){
        int idx=tid+i*NTHR,r=idx&31,w=idx>>5,k=w*2;
        float v0,v1;
        if(r<16){v0=__ldg(&Whz[(size_t)k*1024+bid*16+r]);v1=__ldg(&Whz[(size_t)(k+1)*1024+bid*16+r]);}
        else    {v0=__ldg(&Whr[(size_t)k*1024+bid*16+r-16]);v1=__ldg(&Whr[(size_t)(k+1)*1024+bid*16+r-16]);}
        *(u32*)&wa[r*1024+(swz(r,w)<<1)]=packu(h16(v0),h16(v1));
    }
#pragma unroll 8
    for(int i=0;i<32;i++){
        int idx=tid+i*NTHR,r=idx&15,w=idx>>4,k=w*2;
        float v0=__ldg(&Whh[(size_t)k*1024+bid*16+r]);
        float v1=__ldg(&Whh[(size_t)(k+1)*1024+bid*16+r]);
        *(u32*)&wb[r*1024+(swz(r,w)<<1)]=packu(h16(v0),h16(v1));
    }
    // ---- init state ----
    {
        int gid=bid*NTHR+tid;
        ((u32*)d_h16)[gid*2]=0u;((u32*)d_h16)[gid*2+1]=0u;
        for(int idx=tid;idx<1024;idx+=NTHR)hl[idx]=0.f;
    }
    gridbar();

    const int b_e=tid>>2;          // epilogue batch (0..63)
    const int cg=(tid&3)*4;        // epilogue local col group
    const int gc0=bid*16+cg;       // global col base

    for(int s=0;s<512;s++){
        // ---- prefetch XP for epilogues ----
        size_t xrow=((size_t)b_e*512+s)*3072;
        float4 xpz=__ldg((const float4*)&d_XP[xrow+gc0]);
        float4 xpr=__ldg((const float4*)&d_XP[xrow+1024+gc0]);
        float4 xpn=__ldg((const float4*)&d_XP[xrow+2048+gc0]);

        // ---- phase A: preact[32 rows][64 b] over k-slice kw*256 ----
        float acc[2][4][4];
#pragma unroll
        for(int mt=0;mt<2;mt++)
#pragma unroll
        for(int nt=0;nt<4;nt++)
#pragma unroll
        for(int q=0;q<4;q++)acc[mt][nt][q]=0.f;
#pragma unroll 4
        for(int i=0;i<16;i++){
            int kk=kw*256+i*16+tk;
            u32 a[2][4],bf[4][2];
#pragma unroll
            for(int nt=0;nt<4;nt++){
                int bb=nw*32+nt*8+g;
                bf[nt][0]=ldcg32(&d_h16[bb*1024+kk]);
                bf[nt][1]=ldcg32(&d_h16[bb*1024+kk+8]);
            }
#pragma unroll
            for(int mt=0;mt<2;mt++){
                int r=mt*16+g;
                a[mt][0]=*(const u32*)&wa[r*1024+(swz(r,kk>>1)<<1)];
                a[mt][1]=*(const u32*)&wa[(r+8)*1024+(swz(r+8,kk>>1)<<1)];
                a[mt][2]=*(const u32*)&wa[r*1024+(swz(r,(kk+8)>>1)<<1)];
                a[mt][3]=*(const u32*)&wa[(r+8)*1024+(swz(r+8,(kk+8)>>1)<<1)];
            }
#pragma unroll
            for(int mt=0;mt<2;mt++)
#pragma unroll
            for(int nt=0;nt<4;nt++)
                mma_f16(acc[mt][nt],a[mt],bf[nt]);
        }
        {
#pragma unroll
            for(int mt=0;mt<2;mt++){
                int r=mt*16+g;
#pragma unroll
                for(int nt=0;nt<4;nt++){
                    int b0=nw*32+nt*8+tk;
                    *(float2*)&red[(kw*32+r)*68+b0]  =make_float2(acc[mt][nt][0],acc[mt][nt][1]);
                    *(float2*)&red[(kw*32+r+8)*68+b0]=make_float2(acc[mt][nt][2],acc[mt][nt][3]);
                }
            }
        }
        __syncthreads();
        // ---- epilogue A: z -> zloc, rh -> global (fp16) ----
        {
            float rh4[4];
#pragma unroll
            for(int j=0;j<4;j++){
                float zs=0.f,rs=0.f;
#pragma unroll
                for(int p=0;p<4;p++){
                    zs+=red[(p*32+cg+j)*68+b_e];
                    rs+=red[(p*32+16+cg+j)*68+b_e];
                }
                float z=sigmoidf(zs+((const float*)&xpz)[j]);
                float r=sigmoidf(rs+((const float*)&xpr)[j]);
                zl[(cg+j)*64+b_e]=z;
                rh4[j]=r*hl[(cg+j)*64+b_e];
            }
            u32 lo=packu(h16(rh4[0]),h16(rh4[1]));
            u32 hi=packu(h16(rh4[2]),h16(rh4[3]));
            *(uint2*)&d_rh16[(size_t)b_e*1024+gc0]=make_uint2(lo,hi);
        }
        gridbar();
        // ---- phase B: n preact [16 rows][64 b] over k-slice kw*256 ----
        float ab[4][4];
#pragma unroll
        for(int nt=0;nt<4;nt++)
#pragma unroll
        for(int q=0;q<4;q++)ab[nt][q]=0.f;
#pragma unroll 4
        for(int i=0;i<16;i++){
            int kk=kw*256+i*16+tk;
            u32 a[4],bf[4][2];
#pragma unroll
            for(int nt=0;nt<4;nt++){
                int bb=nw*32+nt*8+g;
                bf[nt][0]=ldcg32(&d_rh16[bb*1024+kk]);
                bf[nt][1]=ldcg32(&d_rh16[bb*1024+kk+8]);
            }
            a[0]=*(const u32*)&wb[g*1024+(swz(g,kk>>1)<<1)];
            a[1]=*(const u32*)&wb[(g+8)*1024+(swz(g+8,kk>>1)<<1)];
            a[2]=*(const u32*)&wb[g*1024+(swz(g,(kk+8)>>1)<<1)];
            a[3]=*(const u32*)&wb[(g+8)*1024+(swz(g+8,(kk+8)>>1)<<1)];
#pragma unroll
            for(int nt=0;nt<4;nt++)
                mma_f16(ab[nt],a,bf[nt]);
        }
        {
#pragma unroll
            for(int nt=0;nt<4;nt++){
                int b0=nw*32+nt*8+tk;
                *(float2*)&red[(kw*32+g)*68+b0]  =make_float2(ab[nt][0],ab[nt][1]);
                *(float2*)&red[(kw*32+g+8)*68+b0]=make_float2(ab[nt][2],ab[nt][3]);
            }
        }
        __syncthreads();
        // ---- epilogue B: h update (local fp32) + global fp16 ----
        {
            float h4[4];
#pragma unroll
            for(int j=0;j<4;j++){
                float ns=0.f;
#pragma unroll
                for(int p=0;p<4;p++)ns+=red[(p*32+cg+j)*68+b_e];
                float n=tanhf(ns+((const float*)&xpn)[j]);
                float z=zl[(cg+j)*64+b_e];
                float h=hl[(cg+j)*64+b_e];
                h4[j]=(1.f-z)*h+z*n;
                hl[(cg+j)*64+b_e]=h4[j];
            }
            u32 lo=packu(h16(h4[0]),h16(h4[1]));
            u32 hi=packu(h16(h4[2]),h16(h4[3]));
            *(uint2*)&d_h16[(size_t)b_e*1024+gc0]=make_uint2(lo,hi);
            if(s==511){
#pragma unroll
                for(int j=0;j<4;j++)d_hF0[(gc0+j)*64+b_e]=h4[j];
            }
        }
        gridbar();
    }
}

// -------- head: out[b][o] = sum_k hF0[k][b]*Wf[k][o] + bf[o] --------
__global__ void head_kernel(const float* __restrict__ Wf,const float* __restrict__ bf,float* __restrict__ out){
    const int b=blockIdx.x,o=threadIdx.x;
    float acc=bf[o];
#pragma unroll 8
    for(int k=0;k<1024;k++)acc+=d_hF0[k*64+b]*Wf[(size_t)k*256+o];
    out[b*256+o]=acc;
}

extern "C" void kernel_launch(void* const* d_in,const int* in_sizes,int n_in,
                              void* d_out,int out_size){
    const float* x  =(const float*)d_in[0];
    const float* Wxz=(const float*)d_in[1];
    const float* Whz=(const float*)d_in[2];
    const float* Wxr=(const float*)d_in[3];
    const float* Whr=(const float*)d_in[4];
    const float* Wxh=(const float*)d_in[5];
    const float* Whh=(const float*)d_in[6];
    const float* bz =(const float*)d_in[7];
    const float* br =(const float*)d_in[8];
    const float* bh =(const float*)d_in[9];
    const float* Wf =(const float*)d_in[10];
    const float* bf =(const float*)d_in[11];
    float* out=(float*)d_out;

    dim3 gx(48,512);
    xproj_kernel<<<gx,256>>>(x,Wxz,Wxr,Wxh,bz,br,bh);
    cudaFuncSetAttribute(gru_kernel,cudaFuncAttributeMaxDynamicSharedMemorySize,SMEM_BYTES);
    gru_kernel<<<GNB,NTHR,SMEM_BYTES>>>(Whz,Whr,Whh);
    head_kernel<<<64,256>>>(Wf,bf,out);
}

// round 17
// speedup vs baseline: 1.2759x; 1.2759x over previous
#include <cuda_runtime.h>
#include <cuda_fp16.h>
#include <cstdint>

#define GNB 64
#define NTHR 256
typedef unsigned u32;
typedef unsigned long long u64;

// -------- device scratch --------
__device__ float d_XP[(size_t)64 * 512 * 3072];            // x-projections (+bias)
__device__ float d_hF0[1024 * 64];                         // final h [col][b] for head
// fp16 state, [b][k] with per-row XOR swizzle (word ^= (b&7)<<2), 16B-aligned
__device__ __align__(16) unsigned short d_h16[64 * 1024];
__device__ __align__(16) unsigned short d_rh16[64 * 1024];
__device__ unsigned d_count;                               // monotone barrier counter

// smem byte offsets (gru kernel)
#define WA_OFF 0          // [32 rows][1024 k] fp16 swizzled (rows 0-15 z-cols, 16-31 r-cols)
#define WB_OFF 65536      // [16 rows][1024 k] fp16 swizzled (n-cols)
#define ST_OFF 98304      // staged state [64 b][1024 k] fp16 swizzled (128KB)
#define MBAR_OFF 229376
#define SMEM_BYTES 229392
#define ST_BYTES 131072

// -------- helpers --------
__device__ __forceinline__ u64 dup2(float x){u64 r;asm("mov.b64 %0,{%1,%1};":"=l"(r):"f"(x));return r;}
__device__ __forceinline__ void fma2(u64&a,u64 x,u64 y){asm("fma.rn.f32x2 %0,%1,%2,%0;":"+l"(a):"l"(x),"l"(y));}
__device__ __forceinline__ float2 unp2(u64 v){float2 f;asm("mov.b64 {%0,%1},%2;":"=f"(f.x),"=f"(f.y):"l"(v));return f;}
__device__ __forceinline__ void lds128(u64&a,u64&b,unsigned ad){asm volatile("ld.shared.v2.u64 {%0,%1},[%2];":"=l"(a),"=l"(b):"r"(ad));}
__device__ __forceinline__ float sigmoidf(float x){return 1.f/(1.f+__expf(-x));}

__device__ __forceinline__ void mma_f16(float* c,const u32* a,const u32* b){
    asm volatile("mma.sync.aligned.m16n8k16.row.col.f32.f16.f16.f32 "
        "{%0,%1,%2,%3},{%4,%5,%6,%7},{%8,%9},{%0,%1,%2,%3};"
        : "+f"(c[0]),"+f"(c[1]),"+f"(c[2]),"+f"(c[3])
        : "r"(a[0]),"r"(a[1]),"r"(a[2]),"r"(a[3]),"r"(b[0]),"r"(b[1]));
}
__device__ __forceinline__ unsigned short h16(float x){
    return __half_as_ushort(__float2half_rn(x));
}
__device__ __forceinline__ u32 packu(unsigned short a,unsigned short b){
    return (u32)a|((u32)b<<16);
}
__device__ __forceinline__ int swz(int row,int w){return w^((row&7)<<2);}
// store one fp16 scalar into swizzled [b][k] global layout
__device__ __forceinline__ void st16g(unsigned short* base,int b,int c,unsigned short v){
    int w=(c>>1)^((b&7)<<2);
    base[(size_t)b*1024+(w<<1)+(c&1)]=v;
}

// single-counter monotone grid barrier (release/acquire), GNB arrivals
__device__ __forceinline__ void gridbar(){
    __syncthreads();
    if(threadIdx.x==0){
        asm volatile("fence.proxy.async;":::"memory");
        unsigned a;
        asm volatile("atom.add.release.gpu.u32 %0,[%1],%2;"
                     :"=r"(a):"l"(&d_count),"r"(1u):"memory");
        unsigned tg=a-(a&(GNB-1))+GNB,cur;
        do{asm volatile("ld.acquire.gpu.u32 %0,[%1];":"=r"(cur):"l"(&d_count));}while((int)(cur-tg)<0);
    }
    __syncthreads();
}

__device__ __forceinline__ void mbar_init(u32 mb,u32 c){
    asm volatile("mbarrier.init.shared.b64 [%0],%1;"::"r"(mb),"r"(c):"memory");
}
__device__ __forceinline__ void mbar_expect(u32 mb,u32 bytes){
    asm volatile("mbarrier.arrive.expect_tx.shared.b64 _,[%0],%1;"::"r"(mb),"r"(bytes):"memory");
}
__device__ __forceinline__ void bulk_copy(u32 dst,const void* src,u32 bytes,u32 mb){
    asm volatile("cp.async.bulk.shared::cta.global.mbarrier::complete_tx::bytes [%0],[%1],%2,[%3];"
        ::"r"(dst),"l"(src),"r"(bytes),"r"(mb):"memory");
}
__device__ __forceinline__ void mbar_wait(u32 mb,u32 par){
    u32 done;
    do{asm volatile("{\n\t.reg .pred p;\n\t"
        "mbarrier.try_wait.parity.acquire.cta.shared::cta.b64 p,[%1],%2,0x989680;\n\t"
        "selp.b32 %0,1,0,p;\n\t}":"=r"(done):"r"(mb),"r"(par):"memory");}while(!done);
}

// -------- xproj (fp32, proven) --------
__global__ void __launch_bounds__(256) xproj_kernel(
    const float* __restrict__ x,
    const float* __restrict__ Wxz,const float* __restrict__ Wxr,const float* __restrict__ Wxh,
    const float* __restrict__ bz,const float* __restrict__ br,const float* __restrict__ bh){
    __shared__ float As[64*68],Bs[64*68];
    const int tid=threadIdx.x,ct=blockIdx.x,rt=blockIdx.y,wsel=ct>>4;
    const float* W=(wsel==0)?Wxz:((wsel==1)?Wxr:Wxh);
    const float* bias=(wsel==0)?bz:((wsel==1)?br:bh);
    const int colbase=(ct&15)*64,row0=rt*64,r4=(tid>>4)*4,c4=(tid&15)*4;
    u64 acc[4][2]={};
    for(int k0=0;k0<256;k0+=64){
        __syncthreads();
#pragma unroll
        for(int i=0;i<4;i++){int q=tid+i*256,rr=q>>4,kq=q&15;
            *(float4*)&As[rr*68+kq*4]=*(const float4*)&x[(size_t)(row0+rr)*256+k0+kq*4];}
#pragma unroll
        for(int i=0;i<4;i++){int q=tid+i*256,kk=q>>4,cq=q&15;
            *(float4*)&Bs[kk*68+cq*4]=*(const float4*)&W[(size_t)(k0+kk)*1024+colbase+cq*4];}
        __syncthreads();
        unsigned bs=(unsigned)__cvta_generic_to_shared(&Bs[c4]);
#pragma unroll 8
        for(int kk=0;kk<64;kk++){
            u64 bL,bH;lds128(bL,bH,bs+kk*68*4);
#pragma unroll
            for(int i=0;i<4;i++){u64 ad=dup2(As[(r4+i)*68+kk]);fma2(acc[i][0],ad,bL);fma2(acc[i][1],ad,bH);}
        }
    }
    float4 bb=*(const float4*)&bias[colbase+c4];
#pragma unroll
    for(int i=0;i<4;i++){
        float2 lo=unp2(acc[i][0]),hi=unp2(acc[i][1]);
        *(float4*)&d_XP[(size_t)(row0+r4+i)*3072+ct*64+c4]=make_float4(lo.x+bb.x,lo.y+bb.y,hi.x+bb.z,hi.y+bb.w);
    }
}

// -------- persistent GRU: 64 blocks, gate-colocated cols, full-K, 2 legs/step --------
__global__ void __launch_bounds__(NTHR,1) gru_kernel(
    const float* __restrict__ Whz,const float* __restrict__ Whr,const float* __restrict__ Whh){
    extern __shared__ char smc[];
    unsigned short* wa=(unsigned short*)(smc+WA_OFF);
    unsigned short* wb=(unsigned short*)(smc+WB_OFF);
    unsigned short* st=(unsigned short*)(smc+ST_OFF);
    const int tid=threadIdx.x,bid=blockIdx.x,wid=tid>>5,lane=tid&31;
    const int g=lane>>2,tk=(lane&3)*2;
    u32 smb; asm("{ .reg .u64 t; cvta.to.shared.u64 t,%1; cvt.u32.u64 %0,t; }":"=r"(smb):"l"((void*)smc));
    const u32 mbar=smb+MBAR_OFF;
    const u32 stu=smb+ST_OFF;

    // ---- weights -> smem fp16 swizzled (R15-proven loaders) ----
#pragma unroll 8
    for(int i=0;i<64;i++){
        int idx=tid+i*NTHR,r=idx&31,w=idx>>5,k=w*2;
        float v0,v1;
        if(r<16){v0=__ldg(&Whz[(size_t)k*1024+bid*16+r]);v1=__ldg(&Whz[(size_t)(k+1)*1024+bid*16+r]);}
        else    {v0=__ldg(&Whr[(size_t)k*1024+bid*16+r-16]);v1=__ldg(&Whr[(size_t)(k+1)*1024+bid*16+r-16]);}
        *(u32*)&wa[r*1024+(swz(r,w)<<1)]=packu(h16(v0),h16(v1));
    }
#pragma unroll 8
    for(int i=0;i<32;i++){
        int idx=tid+i*NTHR,r=idx&15,w=idx>>4,k=w*2;
        float v0=__ldg(&Whh[(size_t)k*1024+bid*16+r]);
        float v1=__ldg(&Whh[(size_t)(k+1)*1024+bid*16+r]);
        *(u32*)&wb[r*1024+(swz(r,w)<<1)]=packu(h16(v0),h16(v1));
    }
    // ---- init state: h16 = 0 globally; per-thread fp32 h regs = 0 ----
    {
        int gid=bid*NTHR+tid;               // 16384 threads x u32 covers d_h16 exactly
        ((u32*)d_h16)[gid]=0u;
    }
    if(tid==0)mbar_init(mbar,1);
    __syncthreads();
    gridbar();

    // per-thread ownership (cols c0=bid*16+g, c1=c0+8; batches b0=wid*8+tk, b1=b0+1)
    const int c0=bid*16+g, c1=c0+8;
    const int b0=wid*8+tk, b1=b0+1;
    float hreg[4]={0.f,0.f,0.f,0.f};        // q: (c0,b0),(c0,b1),(c1,b0),(c1,b1)
    float zreg[4];
    u32 par=0;

    for(int s=0;s<512;s++){
        // ---- leg 1: stage h (all blocks read same 128KB) ----
        if(tid==0){
            mbar_expect(mbar,ST_BYTES);
            bulk_copy(stu,d_h16,ST_BYTES,mbar);
        }
        // prefetch XP for all 3 gates (12 scalars)
        size_t xr0=((size_t)b0*512+s)*3072, xr1=((size_t)b1*512+s)*3072;
        float xpz[4]={__ldg(&d_XP[xr0+c0]),__ldg(&d_XP[xr1+c0]),__ldg(&d_XP[xr0+c1]),__ldg(&d_XP[xr1+c1])};
        float xpr[4]={__ldg(&d_XP[xr0+1024+c0]),__ldg(&d_XP[xr1+1024+c0]),__ldg(&d_XP[xr0+1024+c1]),__ldg(&d_XP[xr1+1024+c1])};
        float xpn[4]={__ldg(&d_XP[xr0+2048+c0]),__ldg(&d_XP[xr1+2048+c0]),__ldg(&d_XP[xr0+2048+c1]),__ldg(&d_XP[xr1+2048+c1])};
        mbar_wait(mbar,par); par^=1;

        // ---- phase A MMA: rows 32 (z|r), n-slice = warp's 8 batches, full K ----
        float acc[2][4][4];
#pragma unroll
        for(int mt=0;mt<2;mt++)
#pragma unroll
        for(int p=0;p<4;p++)
#pragma unroll
        for(int q=0;q<4;q++)acc[mt][p][q]=0.f;
#pragma unroll 4
        for(int i=0;i<64;i++){
            int kk=i*16+tk, w0=kk>>1, w1=w0+4, p=i&3;
            u32 a[2][4],bf[2];
            {
                int bb=wid*8+g;
                bf[0]=*(const u32*)&st[bb*1024+(swz(bb,w0)<<1)];
                bf[1]=*(const u32*)&st[bb*1024+(swz(bb,w1)<<1)];
            }
#pragma unroll
            for(int mt=0;mt<2;mt++){
                int r=mt*16+g;
                a[mt][0]=*(const u32*)&wa[r*1024+(swz(r,w0)<<1)];
                a[mt][1]=*(const u32*)&wa[(r+8)*1024+(swz(r+8,w0)<<1)];
                a[mt][2]=*(const u32*)&wa[r*1024+(swz(r,w1)<<1)];
                a[mt][3]=*(const u32*)&wa[(r+8)*1024+(swz(r+8,w1)<<1)];
            }
            mma_f16(acc[0][p],a[0],bf);
            mma_f16(acc[1][p],a[1],bf);
        }
        // ---- epilogue A (all-local): z regs, rh -> global fp16 swizzled ----
        {
#pragma unroll
            for(int q=0;q<4;q++){
                float za=acc[0][0][q]+acc[0][1][q]+acc[0][2][q]+acc[0][3][q];
                float ra=acc[1][0][q]+acc[1][1][q]+acc[1][2][q]+acc[1][3][q];
                zreg[q]=sigmoidf(za+xpz[q]);
                float r=sigmoidf(ra+xpr[q]);
                float rh=r*hreg[q];
                int c=(q<2)?c0:c1, b=(q&1)?b1:b0;
                st16g(d_rh16,b,c,h16(rh));
            }
        }
        gridbar();

        // ---- leg 2: stage rh ----
        if(tid==0){
            mbar_expect(mbar,ST_BYTES);
            bulk_copy(stu,d_rh16,ST_BYTES,mbar);
        }
        mbar_wait(mbar,par); par^=1;

        // ---- phase B MMA: rows 16 (n), full K ----
        float ab[4][4];
#pragma unroll
        for(int p=0;p<4;p++)
#pragma unroll
        for(int q=0;q<4;q++)ab[p][q]=0.f;
#pragma unroll 4
        for(int i=0;i<64;i++){
            int kk=i*16+tk, w0=kk>>1, w1=w0+4, p=i&3;
            u32 a[4],bf[2];
            {
                int bb=wid*8+g;
                bf[0]=*(const u32*)&st[bb*1024+(swz(bb,w0)<<1)];
                bf[1]=*(const u32*)&st[bb*1024+(swz(bb,w1)<<1)];
            }
            a[0]=*(const u32*)&wb[g*1024+(swz(g,w0)<<1)];
            a[1]=*(const u32*)&wb[(g+8)*1024+(swz(g+8,w0)<<1)];
            a[2]=*(const u32*)&wb[g*1024+(swz(g,w1)<<1)];
            a[3]=*(const u32*)&wb[(g+8)*1024+(swz(g+8,w1)<<1)];
            mma_f16(ab[p],a,bf);
        }
        // ---- epilogue B (all-local): h update in regs, h -> global fp16 ----
        {
#pragma unroll
            for(int q=0;q<4;q++){
                float na=ab[0][q]+ab[1][q]+ab[2][q]+ab[3][q];
                float n=tanhf(na+xpn[q]);
                hreg[q]=(1.f-zreg[q])*hreg[q]+zreg[q]*n;
                int c=(q<2)?c0:c1, b=(q&1)?b1:b0;
                st16g(d_h16,b,c,h16(hreg[q]));
                if(s==511)d_hF0[c*64+b]=hreg[q];
            }
        }
        gridbar();
    }
}

// -------- head: out[b][o] = sum_k hF0[k][b]*Wf[k][o] + bf[o] --------
__global__ void head_kernel(const float* __restrict__ Wf,const float* __restrict__ bf,float* __restrict__ out){
    const int b=blockIdx.x,o=threadIdx.x;
    float acc=bf[o];
#pragma unroll 8
    for(int k=0;k<1024;k++)acc+=d_hF0[k*64+b]*Wf[(size_t)k*256+o];
    out[b*256+o]=acc;
}

extern "C" void kernel_launch(void* const* d_in,const int* in_sizes,int n_in,
                              void* d_out,int out_size){
    const float* x  =(const float*)d_in[0];
    const float* Wxz=(const float*)d_in[1];
    const float* Whz=(const float*)d_in[2];
    const float* Wxr=(const float*)d_in[3];
    const float* Whr=(const float*)d_in[4];
    const float* Wxh=(const float*)d_in[5];
    const float* Whh=(const float*)d_in[6];
    const float* bz =(const float*)d_in[7];
    const float* br =(const float*)d_in[8];
    const float* bh =(const float*)d_in[9];
    const float* Wf =(const float*)d_in[10];
    const float* bf =(const float*)d_in[11];
    float* out=(float*)d_out;

    dim3 gx(48,512);
    xproj_kernel<<<gx,256>>>(x,Wxz,Wxr,Wxh,bz,br,bh);
    cudaFuncSetAttribute(gru_kernel,cudaFuncAttributeMaxDynamicSharedMemorySize,SMEM_BYTES);
    gru_kernel<<<GNB,NTHR,SMEM_BYTES>>>(Whz,Whr,Whh);
    head_kernel<<<64,256>>>(Wf,bf,out);
}